// round 6
// baseline (speedup 1.0000x reference)
#include <cuda_runtime.h>
#include <cstdint>

#define Bb 2
#define Hh 16
#define Ss 2048
#define Dd 64
#define BH (Bb*Hh)
#define SCALE 0.125f

// ---------------- global scratch ----------------
__device__ unsigned int g_maskbits[(size_t)Bb * Ss * Ss / 32];
#define TILE_ULL 1024
__device__ unsigned long long gKhi[(size_t)BH * 32 * TILE_ULL];
__device__ unsigned long long gKlo[(size_t)BH * 32 * TILE_ULL];
__device__ unsigned long long gVhi[(size_t)BH * 32 * TILE_ULL];
__device__ unsigned long long gVlo[(size_t)BH * 32 * TILE_ULL];

__global__ void pack_mask_kernel(const int* __restrict__ masks)
{
    int e = blockIdx.x * 256 + threadIdx.x;
    int val = masks[e] != 0;
    unsigned bal = __ballot_sync(0xFFFFFFFFu, val);
    if ((threadIdx.x & 31) == 0) g_maskbits[e >> 5] = bal;
}

// ---------------- helpers ----------------
__device__ __forceinline__ uint32_t smem_u32(const void* p) {
    uint32_t a;
    asm("{ .reg .u64 t; cvta.to.shared.u64 t, %1; cvt.u32.u64 %0, t; }" : "=r"(a) : "l"(p));
    return a;
}
__device__ __forceinline__ uint32_t packpair(float s0, float s1) {
    uint32_t p;  // low 16 = s0, high 16 = s1
    asm("cvt.rn.bf16x2.f32 %0, %1, %2;" : "=r"(p) : "f"(s1), "f"(s0));
    return p;
}
__device__ __forceinline__ uint32_t packhi(float s0, float s1, float& h0, float& h1) {
    uint32_t p = packpair(s0, s1);
    h0 = __uint_as_float(p << 16);
    h1 = __uint_as_float(p & 0xFFFF0000u);
    return p;
}
__device__ __forceinline__ int goff(int row, int gidx) {
    return row * 16 + (gidx ^ ((row & 3) << 2));
}
__device__ __forceinline__ void mma16(float4& d, uint32_t a0, uint32_t a1, uint32_t a2,
                                      uint32_t a3, uint32_t b0, uint32_t b1)
{
    asm volatile(
        "mma.sync.aligned.m16n8k16.row.col.f32.bf16.bf16.f32 "
        "{%0,%1,%2,%3}, {%4,%5,%6,%7}, {%8,%9}, {%0,%1,%2,%3};"
        : "+f"(d.x), "+f"(d.y), "+f"(d.z), "+f"(d.w)
        : "r"(a0), "r"(a1), "r"(a2), "r"(a3), "r"(b0), "r"(b1));
}

// ---------------- prepasses ----------------
__global__ void split_k_kernel(const float* __restrict__ k)
{
    int idx = blockIdx.x * 256 + threadIdx.x;    // BH*2048*16
    int gidx = idx & 15;
    int tglob = (idx >> 4) & 2047;
    int bh = idx >> 15;
    int ks = gidx >> 2, tig = gidx & 3;
    const float* kr = k + ((size_t)bh * Ss + tglob) * Dd + 16 * ks + 2 * tig;
    float2 p0 = *(const float2*)kr;
    float2 p1 = *(const float2*)(kr + 8);
    float h00, h01, h10, h11;
    uint32_t b0h = packhi(p0.x, p0.y, h00, h01);
    uint32_t b1h = packhi(p1.x, p1.y, h10, h11);
    uint32_t b0l = packpair(p0.x - h00, p0.y - h01);
    uint32_t b1l = packpair(p1.x - h10, p1.y - h11);
    int kt = tglob >> 6, tl = tglob & 63;
    size_t base = ((size_t)bh * 32 + kt) * TILE_ULL + goff(tl, gidx);
    gKhi[base] = (unsigned long long)b0h | ((unsigned long long)b1h << 32);
    gKlo[base] = (unsigned long long)b0l | ((unsigned long long)b1l << 32);
}

__global__ void split_vt_kernel(const float* __restrict__ v)
{
    int idx = blockIdx.x * 256 + threadIdx.x;    // BH*32*16*64
    int d  = idx & 63;
    int gidx = (idx >> 6) & 15;
    int kt = (idx >> 10) & 31;
    int bh = idx >> 15;
    int ks = gidx >> 2, tig = gidx & 3;
    int t0 = kt * 64 + 16 * ks + 2 * tig;
    const float* vb = v + (size_t)bh * Ss * Dd + d;
    float v0 = vb[(size_t)t0 * Dd];
    float v1 = vb[(size_t)(t0 + 1) * Dd];
    float v2 = vb[(size_t)(t0 + 8) * Dd];
    float v3 = vb[(size_t)(t0 + 9) * Dd];
    float h0, h1, h2, h3;
    uint32_t b0h = packhi(v0, v1, h0, h1);
    uint32_t b1h = packhi(v2, v3, h2, h3);
    uint32_t b0l = packpair(v0 - h0, v1 - h1);
    uint32_t b1l = packpair(v2 - h2, v3 - h3);
    size_t base = ((size_t)bh * 32 + kt) * TILE_ULL + goff(d, gidx);
    gVhi[base] = (unsigned long long)b0h | ((unsigned long long)b1h << 32);
    gVlo[base] = (unsigned long long)b0l | ((unsigned long long)b1l << 32);
}

// ---------------- smem layout: 3-stage ring ----------------
// stage s at BUF + s*32768: [Khi 8K][Klo 8K][Vhi 8K][Vlo 8K]
#define BUF  0u
#define SINV 98304u
#define SMEM_TOTAL (98304 + 512)

__global__ void __launch_bounds__(256, 2)
sdpa_main_kernel(const float* __restrict__ q, float* __restrict__ out)
{
    extern __shared__ char smc[];
    const uint32_t sb = smem_u32(smc);
    float* sInv = (float*)(smc + SINV);

    const int tid  = threadIdx.x;
    const int lane = tid & 31;
    const int w    = tid >> 5;
    const int g    = lane >> 2;
    const int tig  = lane & 3;

    const int bh = blockIdx.y;
    const int b  = bh >> 4;
    const int s0 = blockIdx.x * 128;

    const float* qg = q + ((size_t)bh * Ss + s0) * Dd;
    float* outg = out + ((size_t)bh * Ss + s0) * Dd;
    float* attg = out + (size_t)BH * Ss * Dd + ((size_t)bh * Ss + s0) * Ss;

    const size_t tilebase = (size_t)bh * 32;

    auto issue = [&](int kt) {
        uint32_t dstb = sb + BUF + (uint32_t)(kt % 3) * 32768u;
        const unsigned long long* srcs[4] = {
            gKhi + (tilebase + kt) * TILE_ULL, gKlo + (tilebase + kt) * TILE_ULL,
            gVhi + (tilebase + kt) * TILE_ULL, gVlo + (tilebase + kt) * TILE_ULL };
        #pragma unroll
        for (int pl = 0; pl < 4; ++pl) {
            const char* src = (const char*)srcs[pl];
            uint32_t dst = dstb + pl * 8192u;
            #pragma unroll
            for (int i = 0; i < 2; ++i) {
                int off = (tid + i * 256) * 16;
                asm volatile("cp.async.cg.shared.global [%0], [%1], 16;"
                             :: "r"(dst + off), "l"(src + off));
            }
        }
        asm volatile("cp.async.commit_group;");
    };

    issue(0);
    issue(1);

    // ---- Q fragments: per-thread direct gmem loads (one-time) ----
    const int r0 = w * 16 + g;
    uint2 qh[4][2], ql[4][2];
    {
        const float* q0 = qg + (size_t)r0 * Dd;
        const float* q8 = qg + (size_t)(r0 + 8) * Dd;
        #pragma unroll
        for (int ks = 0; ks < 4; ++ks) {
            int c = 16 * ks + 2 * tig;
            #pragma unroll
            for (int half = 0; half < 2; ++half) {
                const float* qr = half ? q8 : q0;
                float2 p0 = *(const float2*)(qr + c);
                float2 p1 = *(const float2*)(qr + c + 8);
                float h00, h01, h10, h11;
                uint32_t b0h = packhi(p0.x, p0.y, h00, h01);
                uint32_t b1h = packhi(p1.x, p1.y, h10, h11);
                qh[ks][half] = make_uint2(b0h, b1h);
                ql[ks][half] = make_uint2(packpair(p0.x - h00, p0.y - h01),
                                          packpair(p1.x - h10, p1.y - h11));
            }
        }
    }

    const unsigned long long* m64 = (const unsigned long long*)g_maskbits;
    const size_t mrow0 = ((size_t)b * Ss + s0 + r0) * (Ss / 64);
    const size_t mrow1 = mrow0 + 8 * (Ss / 64);

    float rs0 = 0.f, rs1 = 0.f;
    float4 po[8];
    #pragma unroll
    for (int j = 0; j < 8; ++j) po[j] = make_float4(0.f, 0.f, 0.f, 0.f);

    float* att0 = attg + (size_t)r0 * Ss;
    float* att1 = attg + (size_t)(r0 + 8) * Ss;

    // precompute per-warp B-row offsets (granule index part that depends on j only)
    for (int kt = 0; kt < 32; ++kt) {
        if (kt < 31) {
            asm volatile("cp.async.wait_group 1;");
        } else {
            asm volatile("cp.async.wait_group 0;");
        }
        __syncthreads();            // stage kt ready for all; stage (kt-1)%3 free
        if (kt < 30) issue(kt + 2); // refill freed stage

        const char* kb  = smc + BUF + (kt % 3) * 32768;
        const char* kbl = kb + 8192;
        const char* vb  = kb + 16384;
        const char* vbl = kb + 24576;

        unsigned long long mw0 = m64[mrow0 + kt];
        unsigned long long mw1 = m64[mrow1 + kt];

        // ---- QK: 128x64 scores via bf16x3 ----
        float4 cf[8];
        #pragma unroll
        for (int j = 0; j < 8; ++j) cf[j] = make_float4(0.f, 0.f, 0.f, 0.f);

        #pragma unroll
        for (int ks = 0; ks < 4; ++ks) {
            uint2 aH0 = qh[ks][0], aH8 = qh[ks][1];
            uint2 aL0 = ql[ks][0], aL8 = ql[ks][1];
            #pragma unroll
            for (int j = 0; j < 8; ++j) {
                int ro = goff(8 * j + g, 4 * ks + tig) * 8;
                uint2 bH = *(const uint2*)(kb + ro);
                uint2 bL = *(const uint2*)(kbl + ro);
                mma16(cf[j], aH0.x, aH8.x, aH0.y, aH8.y, bH.x, bH.y);
                mma16(cf[j], aH0.x, aH8.x, aH0.y, aH8.y, bL.x, bL.y);
                mma16(cf[j], aL0.x, aL8.x, aL0.y, aL8.y, bH.x, bH.y);
            }
        }

        // ---- epilogue fused with PV (C-frag -> A-frag identity) ----
        const int t0k = kt * 64;
        #pragma unroll
        for (int ks2 = 0; ks2 < 4; ++ks2) {
            uint32_t pa[2][2], pb[2][2];
            #pragma unroll
            for (int u = 0; u < 2; ++u) {
                int j = 2 * ks2 + u;
                int c0 = 8 * j + 2 * tig;
                float4 c = cf[j];
                float s00 = ((mw0 >> c0) & 1ull)       ? c.x * SCALE : -1e-12f;
                float s01 = ((mw0 >> (c0 + 1)) & 1ull) ? c.y * SCALE : -1e-12f;
                float s10 = ((mw1 >> c0) & 1ull)       ? c.z * SCALE : -1e-12f;
                float s11 = ((mw1 >> (c0 + 1)) & 1ull) ? c.w * SCALE : -1e-12f;
                float e00 = __expf(s00), e01 = __expf(s01);
                float e10 = __expf(s10), e11 = __expf(s11);
                rs0 += e00 + e01; rs1 += e10 + e11;
                *(float2*)(att0 + t0k + c0) = make_float2(e00, e01);
                *(float2*)(att1 + t0k + c0) = make_float2(e10, e11);
                float h0, h1;
                pa[u][0] = packhi(s00, s01, h0, h1);
                pa[u][1] = packpair(s00 - h0, s01 - h1);
                pb[u][0] = packhi(s10, s11, h0, h1);
                pb[u][1] = packpair(s10 - h0, s11 - h1);
            }
            #pragma unroll
            for (int j = 0; j < 8; ++j) {
                int ro = goff(8 * j + g, 4 * ks2 + tig) * 8;
                uint2 bH = *(const uint2*)(vb + ro);
                uint2 bL = *(const uint2*)(vbl + ro);
                mma16(po[j], pa[0][0], pb[0][0], pa[1][0], pb[1][0], bH.x, bH.y);
                mma16(po[j], pa[0][0], pb[0][0], pa[1][0], pb[1][0], bL.x, bL.y);
                mma16(po[j], pa[0][1], pb[0][1], pa[1][1], pb[1][1], bH.x, bH.y);
            }
        }
    }

    // ---- write output ----
    #pragma unroll
    for (int j = 0; j < 8; ++j) {
        int c0 = 8 * j + 2 * tig;
        *(float2*)(outg + (size_t)r0 * Dd + c0)       = make_float2(po[j].x, po[j].y);
        *(float2*)(outg + (size_t)(r0 + 8) * Dd + c0) = make_float2(po[j].z, po[j].w);
    }

    // ---- rowsum reduce + normalize att ----
    rs0 += __shfl_xor_sync(0xFFFFFFFFu, rs0, 1);
    rs0 += __shfl_xor_sync(0xFFFFFFFFu, rs0, 2);
    rs1 += __shfl_xor_sync(0xFFFFFFFFu, rs1, 1);
    rs1 += __shfl_xor_sync(0xFFFFFFFFu, rs1, 2);
    if (tig == 0) {
        sInv[r0]     = 1.f / rs0;
        sInv[r0 + 8] = 1.f / rs1;
    }
    __syncthreads();

    for (int r = 0; r < 128; ++r) {
        float iv = sInv[r];
        float* row = attg + (size_t)r * Ss + tid * 8;
        float4 a = *(const float4*)(row);
        float4 c = *(const float4*)(row + 4);
        a.x *= iv; a.y *= iv; a.z *= iv; a.w *= iv;
        c.x *= iv; c.y *= iv; c.z *= iv; c.w *= iv;
        *(float4*)(row)     = a;
        *(float4*)(row + 4) = c;
    }
}

extern "C" void kernel_launch(void* const* d_in, const int* in_sizes, int n_in,
                              void* d_out, int out_size)
{
    const float* q = (const float*)d_in[0];
    const float* k = (const float*)d_in[1];
    const float* v = (const float*)d_in[2];
    const int* masks = (const int*)d_in[3];
    float* out = (float*)d_out;

    pack_mask_kernel<<<(Bb * Ss * Ss) / 256, 256>>>(masks);
    split_k_kernel<<<(BH * Ss * 16) / 256, 256>>>(k);
    split_vt_kernel<<<(BH * 32 * 16 * 64) / 256, 256>>>(v);

    cudaFuncSetAttribute(sdpa_main_kernel,
                         cudaFuncAttributeMaxDynamicSharedMemorySize, SMEM_TOTAL);

    dim3 grid(Ss / 128, BH);   // (16, 32)
    sdpa_main_kernel<<<grid, 256, SMEM_TOTAL>>>(q, out);
}

// round 7
// speedup vs baseline: 1.0101x; 1.0101x over previous
#include <cuda_runtime.h>
#include <cstdint>

#define Bb 2
#define Hh 16
#define Ss 2048
#define Dd 64
#define BH (Bb*Hh)
#define SCALE 0.125f

// ---------------- global scratch ----------------
__device__ unsigned int g_maskbits[(size_t)Bb * Ss * Ss / 32];
#define TILE_ULL 1024
__device__ unsigned long long gKhi[(size_t)BH * 32 * TILE_ULL];
__device__ unsigned long long gKlo[(size_t)BH * 32 * TILE_ULL];
__device__ unsigned long long gVhi[(size_t)BH * 32 * TILE_ULL];
__device__ unsigned long long gVlo[(size_t)BH * 32 * TILE_ULL];

__global__ void pack_mask_kernel(const int* __restrict__ masks)
{
    int e = blockIdx.x * 256 + threadIdx.x;
    int val = masks[e] != 0;
    unsigned bal = __ballot_sync(0xFFFFFFFFu, val);
    if ((threadIdx.x & 31) == 0) g_maskbits[e >> 5] = bal;
}

// ---------------- helpers ----------------
__device__ __forceinline__ uint32_t smem_u32(const void* p) {
    uint32_t a;
    asm("{ .reg .u64 t; cvta.to.shared.u64 t, %1; cvt.u32.u64 %0, t; }" : "=r"(a) : "l"(p));
    return a;
}
__device__ __forceinline__ uint32_t packpair(float s0, float s1) {
    uint32_t p;  // low 16 = s0, high 16 = s1
    asm("cvt.rn.bf16x2.f32 %0, %1, %2;" : "=r"(p) : "f"(s1), "f"(s0));
    return p;
}
__device__ __forceinline__ uint32_t packhi(float s0, float s1, float& h0, float& h1) {
    uint32_t p = packpair(s0, s1);
    h0 = __uint_as_float(p << 16);
    h1 = __uint_as_float(p & 0xFFFF0000u);
    return p;
}
__device__ __forceinline__ int goff(int row, int gidx) {
    return row * 16 + (gidx ^ ((row & 3) << 2));
}
__device__ __forceinline__ void mma16(float4& d, uint32_t a0, uint32_t a1, uint32_t a2,
                                      uint32_t a3, uint32_t b0, uint32_t b1)
{
    asm volatile(
        "mma.sync.aligned.m16n8k16.row.col.f32.bf16.bf16.f32 "
        "{%0,%1,%2,%3}, {%4,%5,%6,%7}, {%8,%9}, {%0,%1,%2,%3};"
        : "+f"(d.x), "+f"(d.y), "+f"(d.z), "+f"(d.w)
        : "r"(a0), "r"(a1), "r"(a2), "r"(a3), "r"(b0), "r"(b1));
}

// ---- packed f32x2 ops ----
__device__ __forceinline__ unsigned long long pk2(float lo, float hi) {
    unsigned long long r;
    asm("mov.b64 %0, {%1, %2};" : "=l"(r) : "f"(lo), "f"(hi));
    return r;
}
__device__ __forceinline__ void upk2(unsigned long long v, float& lo, float& hi) {
    asm("mov.b64 {%0, %1}, %2;" : "=f"(lo), "=f"(hi) : "l"(v));
}
__device__ __forceinline__ unsigned long long fma2(unsigned long long a,
                                                   unsigned long long b,
                                                   unsigned long long c) {
    unsigned long long d;
    asm("fma.rn.f32x2 %0, %1, %2, %3;" : "=l"(d) : "l"(a), "l"(b), "l"(c));
    return d;
}
__device__ __forceinline__ unsigned long long mul2(unsigned long long a,
                                                   unsigned long long b) {
    unsigned long long d;
    asm("mul.rn.f32x2 %0, %1, %2;" : "=l"(d) : "l"(a), "l"(b));
    return d;
}
__device__ __forceinline__ unsigned long long add2(unsigned long long a,
                                                   unsigned long long b) {
    unsigned long long d;
    asm("add.rn.f32x2 %0, %1, %2;" : "=l"(d) : "l"(a), "l"(b));
    return d;
}
__device__ __forceinline__ float ex2m(float x) {   // MUFU.EX2
    float r;
    asm("ex2.approx.f32 %0, %1;" : "=f"(r) : "f"(x));
    return r;
}

#define L2E 1.4426950408889634f
#define MGC 12582912.0f     // 1.5 * 2^23

// exp(a), exp(b) on the FMA pipe via packed f32x2 (no MUFU)
__device__ __forceinline__ void exp_pair_fma(float a, float b, float& ea, float& eb)
{
    unsigned long long x2  = pk2(a, b);
    unsigned long long l2  = pk2(L2E, L2E);
    unsigned long long t2  = fma2(x2, l2, pk2(MGC, MGC));     // round(x*l2e) in low bits
    unsigned long long g2  = add2(t2, pk2(-MGC, -MGC));       // n as float
    unsigned long long h2  = mul2(x2, l2);
    unsigned long long f2  = fma2(g2, pk2(-1.f, -1.f), h2);   // f = x*l2e - n, [-0.5,0.5]
    unsigned long long p2  = fma2(f2, pk2(0.00961813f, 0.00961813f),
                                       pk2(0.0555041f, 0.0555041f));
    p2 = fma2(f2, p2, pk2(0.2402265f, 0.2402265f));
    p2 = fma2(f2, p2, pk2(0.6931472f, 0.6931472f));
    p2 = fma2(f2, p2, pk2(1.0f, 1.0f));
    float pa, pb, ta, tb;
    upk2(p2, pa, pb);
    upk2(t2, ta, tb);
    int ra = __float_as_int(pa) + (__float_as_int(ta) << 23);  // 2^n scale via exponent add
    int rb = __float_as_int(pb) + (__float_as_int(tb) << 23);
    ea = __int_as_float(ra);
    eb = __int_as_float(rb);
}

// ---------------- prepasses ----------------
__global__ void split_k_kernel(const float* __restrict__ k)
{
    int idx = blockIdx.x * 256 + threadIdx.x;    // BH*2048*16
    int gidx = idx & 15;
    int tglob = (idx >> 4) & 2047;
    int bh = idx >> 15;
    int ks = gidx >> 2, tig = gidx & 3;
    const float* kr = k + ((size_t)bh * Ss + tglob) * Dd + 16 * ks + 2 * tig;
    float2 p0 = *(const float2*)kr;
    float2 p1 = *(const float2*)(kr + 8);
    float h00, h01, h10, h11;
    uint32_t b0h = packhi(p0.x, p0.y, h00, h01);
    uint32_t b1h = packhi(p1.x, p1.y, h10, h11);
    uint32_t b0l = packpair(p0.x - h00, p0.y - h01);
    uint32_t b1l = packpair(p1.x - h10, p1.y - h11);
    int kt = tglob >> 6, tl = tglob & 63;
    size_t base = ((size_t)bh * 32 + kt) * TILE_ULL + goff(tl, gidx);
    gKhi[base] = (unsigned long long)b0h | ((unsigned long long)b1h << 32);
    gKlo[base] = (unsigned long long)b0l | ((unsigned long long)b1l << 32);
}

__global__ void split_vt_kernel(const float* __restrict__ v)
{
    int idx = blockIdx.x * 256 + threadIdx.x;    // BH*32*16*64
    int d  = idx & 63;
    int gidx = (idx >> 6) & 15;
    int kt = (idx >> 10) & 31;
    int bh = idx >> 15;
    int ks = gidx >> 2, tig = gidx & 3;
    int t0 = kt * 64 + 16 * ks + 2 * tig;
    const float* vb = v + (size_t)bh * Ss * Dd + d;
    float v0 = vb[(size_t)t0 * Dd];
    float v1 = vb[(size_t)(t0 + 1) * Dd];
    float v2 = vb[(size_t)(t0 + 8) * Dd];
    float v3 = vb[(size_t)(t0 + 9) * Dd];
    float h0, h1, h2, h3;
    uint32_t b0h = packhi(v0, v1, h0, h1);
    uint32_t b1h = packhi(v2, v3, h2, h3);
    uint32_t b0l = packpair(v0 - h0, v1 - h1);
    uint32_t b1l = packpair(v2 - h2, v3 - h3);
    size_t base = ((size_t)bh * 32 + kt) * TILE_ULL + goff(d, gidx);
    gVhi[base] = (unsigned long long)b0h | ((unsigned long long)b1h << 32);
    gVlo[base] = (unsigned long long)b0l | ((unsigned long long)b1l << 32);
}

// ---------------- smem layout: 3-stage ring ----------------
#define BUF  0u
#define SINV 98304u
#define SMEM_TOTAL (98304 + 512)

__global__ void __launch_bounds__(256, 2)
sdpa_main_kernel(const float* __restrict__ q, float* __restrict__ out)
{
    extern __shared__ char smc[];
    const uint32_t sb = smem_u32(smc);
    float* sInv = (float*)(smc + SINV);

    const int tid  = threadIdx.x;
    const int lane = tid & 31;
    const int w    = tid >> 5;
    const int g    = lane >> 2;
    const int tig  = lane & 3;

    const int bh = blockIdx.y;
    const int b  = bh >> 4;
    const int s0 = blockIdx.x * 128;

    const float* qg = q + ((size_t)bh * Ss + s0) * Dd;
    float* outg = out + ((size_t)bh * Ss + s0) * Dd;
    float* attg = out + (size_t)BH * Ss * Dd + ((size_t)bh * Ss + s0) * Ss;

    const size_t tilebase = (size_t)bh * 32;

    auto issue = [&](int kt) {
        uint32_t dstb = sb + BUF + (uint32_t)(kt % 3) * 32768u;
        const unsigned long long* srcs[4] = {
            gKhi + (tilebase + kt) * TILE_ULL, gKlo + (tilebase + kt) * TILE_ULL,
            gVhi + (tilebase + kt) * TILE_ULL, gVlo + (tilebase + kt) * TILE_ULL };
        #pragma unroll
        for (int pl = 0; pl < 4; ++pl) {
            const char* src = (const char*)srcs[pl];
            uint32_t dst = dstb + pl * 8192u;
            #pragma unroll
            for (int i = 0; i < 2; ++i) {
                int off = (tid + i * 256) * 16;
                asm volatile("cp.async.cg.shared.global [%0], [%1], 16;"
                             :: "r"(dst + off), "l"(src + off));
            }
        }
        asm volatile("cp.async.commit_group;");
    };

    issue(0);
    issue(1);

    // ---- Q fragments: per-thread direct gmem loads (one-time) ----
    const int r0 = w * 16 + g;
    uint2 qh[4][2], ql[4][2];
    {
        const float* q0 = qg + (size_t)r0 * Dd;
        const float* q8 = qg + (size_t)(r0 + 8) * Dd;
        #pragma unroll
        for (int ks = 0; ks < 4; ++ks) {
            int c = 16 * ks + 2 * tig;
            #pragma unroll
            for (int half = 0; half < 2; ++half) {
                const float* qr = half ? q8 : q0;
                float2 p0 = *(const float2*)(qr + c);
                float2 p1 = *(const float2*)(qr + c + 8);
                float h00, h01, h10, h11;
                uint32_t b0h = packhi(p0.x, p0.y, h00, h01);
                uint32_t b1h = packhi(p1.x, p1.y, h10, h11);
                qh[ks][half] = make_uint2(b0h, b1h);
                ql[ks][half] = make_uint2(packpair(p0.x - h00, p0.y - h01),
                                          packpair(p1.x - h10, p1.y - h11));
            }
        }
    }

    const unsigned long long* m64 = (const unsigned long long*)g_maskbits;
    const size_t mrow0 = ((size_t)b * Ss + s0 + r0) * (Ss / 64);
    const size_t mrow1 = mrow0 + 8 * (Ss / 64);

    float rs0 = 0.f, rs1 = 0.f;
    float4 po[8];
    #pragma unroll
    for (int j = 0; j < 8; ++j) po[j] = make_float4(0.f, 0.f, 0.f, 0.f);

    float* att0 = attg + (size_t)r0 * Ss;
    float* att1 = attg + (size_t)(r0 + 8) * Ss;

    for (int kt = 0; kt < 32; ++kt) {
        if (kt < 31) {
            asm volatile("cp.async.wait_group 1;");
        } else {
            asm volatile("cp.async.wait_group 0;");
        }
        __syncthreads();
        if (kt < 30) issue(kt + 2);

        const char* kb  = smc + BUF + (kt % 3) * 32768;
        const char* kbl = kb + 8192;
        const char* vb  = kb + 16384;
        const char* vbl = kb + 24576;

        unsigned long long mw0 = m64[mrow0 + kt];
        unsigned long long mw1 = m64[mrow1 + kt];

        // ---- QK: 128x64 scores via bf16x3 ----
        float4 cf[8];
        #pragma unroll
        for (int j = 0; j < 8; ++j) cf[j] = make_float4(0.f, 0.f, 0.f, 0.f);

        #pragma unroll
        for (int ks = 0; ks < 4; ++ks) {
            uint2 aH0 = qh[ks][0], aH8 = qh[ks][1];
            uint2 aL0 = ql[ks][0], aL8 = ql[ks][1];
            #pragma unroll
            for (int j = 0; j < 8; ++j) {
                int ro = goff(8 * j + g, 4 * ks + tig) * 8;
                uint2 bH = *(const uint2*)(kb + ro);
                uint2 bL = *(const uint2*)(kbl + ro);
                mma16(cf[j], aH0.x, aH8.x, aH0.y, aH8.y, bH.x, bH.y);
                mma16(cf[j], aH0.x, aH8.x, aH0.y, aH8.y, bL.x, bL.y);
                mma16(cf[j], aL0.x, aL8.x, aL0.y, aL8.y, bH.x, bH.y);
            }
        }

        // ---- epilogue fused with PV; exp split 75% MUFU / 25% FMA poly ----
        const int t0k = kt * 64;
        #pragma unroll
        for (int ks2 = 0; ks2 < 4; ++ks2) {
            uint32_t pa[2][2], pb[2][2];
            #pragma unroll
            for (int u = 0; u < 2; ++u) {
                int j = 2 * ks2 + u;
                int c0 = 8 * j + 2 * tig;
                float4 c = cf[j];
                float s00 = ((mw0 >> c0) & 1ull)       ? c.x * SCALE : -1e-12f;
                float s01 = ((mw0 >> (c0 + 1)) & 1ull) ? c.y * SCALE : -1e-12f;
                float s10 = ((mw1 >> c0) & 1ull)       ? c.z * SCALE : -1e-12f;
                float s11 = ((mw1 >> (c0 + 1)) & 1ull) ? c.w * SCALE : -1e-12f;

                float e00, e01, e10, e11;
                {
                    // MUFU path for (s00,s10) always: packed arg scaling
                    unsigned long long a2 = mul2(pk2(s00, s10), pk2(L2E, L2E));
                    float a0, a1;
                    upk2(a2, a0, a1);
                    e00 = ex2m(a0);
                    e10 = ex2m(a1);
                }
                if (u == 0) {
                    // MUFU path for (s01,s11)
                    unsigned long long a2 = mul2(pk2(s01, s11), pk2(L2E, L2E));
                    float a0, a1;
                    upk2(a2, a0, a1);
                    e01 = ex2m(a0);
                    e11 = ex2m(a1);
                } else {
                    // FMA-pipe poly path for (s01,s11)
                    exp_pair_fma(s01, s11, e01, e11);
                }
                rs0 += e00 + e01; rs1 += e10 + e11;
                *(float2*)(att0 + t0k + c0) = make_float2(e00, e01);
                *(float2*)(att1 + t0k + c0) = make_float2(e10, e11);

                float h0, h1;
                pa[u][0] = packhi(s00, s01, h0, h1);
                pa[u][1] = packpair(s00 - h0, s01 - h1);
                pb[u][0] = packhi(s10, s11, h0, h1);
                pb[u][1] = packpair(s10 - h0, s11 - h1);
            }
            #pragma unroll
            for (int j = 0; j < 8; ++j) {
                int ro = goff(8 * j + g, 4 * ks2 + tig) * 8;
                uint2 bH = *(const uint2*)(vb + ro);
                uint2 bL = *(const uint2*)(vbl + ro);
                mma16(po[j], pa[0][0], pb[0][0], pa[1][0], pb[1][0], bH.x, bH.y);
                mma16(po[j], pa[0][0], pb[0][0], pa[1][0], pb[1][0], bL.x, bL.y);
                mma16(po[j], pa[0][1], pb[0][1], pa[1][1], pb[1][1], bH.x, bH.y);
            }
        }
    }

    // ---- write output ----
    #pragma unroll
    for (int j = 0; j < 8; ++j) {
        int c0 = 8 * j + 2 * tig;
        *(float2*)(outg + (size_t)r0 * Dd + c0)       = make_float2(po[j].x, po[j].y);
        *(float2*)(outg + (size_t)(r0 + 8) * Dd + c0) = make_float2(po[j].z, po[j].w);
    }

    // ---- rowsum reduce + normalize att ----
    rs0 += __shfl_xor_sync(0xFFFFFFFFu, rs0, 1);
    rs0 += __shfl_xor_sync(0xFFFFFFFFu, rs0, 2);
    rs1 += __shfl_xor_sync(0xFFFFFFFFu, rs1, 1);
    rs1 += __shfl_xor_sync(0xFFFFFFFFu, rs1, 2);
    if (tig == 0) {
        sInv[r0]     = 1.f / rs0;
        sInv[r0 + 8] = 1.f / rs1;
    }
    __syncthreads();

    for (int r = 0; r < 128; ++r) {
        float iv = sInv[r];
        float* row = attg + (size_t)r * Ss + tid * 8;
        float4 a = *(const float4*)(row);
        float4 c = *(const float4*)(row + 4);
        a.x *= iv; a.y *= iv; a.z *= iv; a.w *= iv;
        c.x *= iv; c.y *= iv; c.z *= iv; c.w *= iv;
        *(float4*)(row)     = a;
        *(float4*)(row + 4) = c;
    }
}

extern "C" void kernel_launch(void* const* d_in, const int* in_sizes, int n_in,
                              void* d_out, int out_size)
{
    const float* q = (const float*)d_in[0];
    const float* k = (const float*)d_in[1];
    const float* v = (const float*)d_in[2];
    const int* masks = (const int*)d_in[3];
    float* out = (float*)d_out;

    pack_mask_kernel<<<(Bb * Ss * Ss) / 256, 256>>>(masks);
    split_k_kernel<<<(BH * Ss * 16) / 256, 256>>>(k);
    split_vt_kernel<<<(BH * 32 * 16 * 64) / 256, 256>>>(v);

    cudaFuncSetAttribute(sdpa_main_kernel,
                         cudaFuncAttributeMaxDynamicSharedMemorySize, SMEM_TOTAL);

    dim3 grid(Ss / 128, BH);   // (16, 32)
    sdpa_main_kernel<<<grid, 256, SMEM_TOTAL>>>(q, out);
}